// round 7
// baseline (speedup 1.0000x reference)
#include <cuda_runtime.h>
#include <math.h>
#include <stdint.h>

#define H 128
#define EPS 1e-9f
#define M_MAX 50000
#define L_MAX 400000
#define MH_MAX (M_MAX * H)

__device__ float g_scratch[12 * (size_t)MH_MAX + 2 * (size_t)L_MAX + 2 * (size_t)M_MAX];

__device__ __forceinline__ float sigmoidf(float x) { return 1.0f / (1.0f + expf(-x)); }

__device__ __forceinline__ float tanh_approx(float x) {
    float y;
    asm("tanh.approx.f32 %0, %1;" : "=f"(y) : "f"(x));
    return y;
}

__device__ __forceinline__ void atomicMaxFloat(float* addr, float v) {
    if (v >= 0.0f) atomicMax((int*)addr, __float_as_int(v));
    else           atomicMin((unsigned int*)addr, __float_as_uint(v));
}

__device__ __forceinline__ uint32_t tf32_rna(float x) {
    uint32_t o;
    asm("cvt.rna.tf32.f32 %0, %1;" : "=r"(o) : "f"(x));
    return o;
}

// ===========================================================================
// Tensor-core GEMM via mma.sync tf32 (HMMA path, compute_103-safe PTX).
// C_w[M,128] = A[M,128] @ W_w[128,128]^T (+ b_w), up to 5 weights per launch
// sharing the staged A tile. Block: 128x128 tile, 256 thr = 8 warps (4m x 2n),
// warp tile 32x64, mma m16n8k8, 16 k-steps. smem rows padded to 132 u32.
// Optional fused LSTM-gate epilogue on the last weight (Uc pass).
// ===========================================================================
#define SMEM_LDA 132
#define GEMM_DSMEM (2 * 128 * SMEM_LDA * 4)

__device__ __forceinline__ void stage_tile_tf32(
    uint32_t* dst, const float* __restrict__ src, int rows_valid) {
    int tid = threadIdx.x;
#pragma unroll
    for (int i = tid; i < 128 * 32; i += 256) {
        int r = i >> 5, c4 = i & 31;
        float4 v = make_float4(0.f, 0.f, 0.f, 0.f);
        if (r < rows_valid) v = ((const float4*)(src + (size_t)r * H))[c4];
        uint4 u;
        u.x = tf32_rna(v.x); u.y = tf32_rna(v.y);
        u.z = tf32_rna(v.z); u.w = tf32_rna(v.w);
        *(uint4*)(dst + r * SMEM_LDA + c4 * 4) = u;
    }
}

__global__ __launch_bounds__(256, 1) void gemm_mma_kernel(
    const float* __restrict__ A, int M, int nW,
    const float* W0, const float* W1, const float* W2, const float* W3, const float* W4,
    const float* b0, const float* b1, const float* b2, const float* b3, const float* b4,
    float* C0, float* C1, float* C2, float* C3, float* C4,
    const float* __restrict__ Wix, const float* __restrict__ Wox,
    const float* __restrict__ Wcx, const float* __restrict__ fpc,
    float* __restrict__ out, int fuse) {
    extern __shared__ uint32_t sm[];
    uint32_t* As = sm;
    uint32_t* Ws = sm + 128 * SMEM_LDA;

    const float* Wp[5] = {W0, W1, W2, W3, W4};
    const float* bp[5] = {b0, b1, b2, b3, b4};
    float*       Cp[5] = {C0, C1, C2, C3, C4};

    const int tid = threadIdx.x;
    const int wid = tid >> 5, lane = tid & 31;
    const int wm = wid & 3, wn = wid >> 2;
    const int gid = lane >> 2, tig = lane & 3;
    const int m0 = blockIdx.x * 128;
    const int rows = min(128, M - m0);
    const int MH = M * H;

    stage_tile_tf32(As, A + (size_t)m0 * H, rows);

    const int rA = wm * 32 + gid;
    const int nB = wn * 64 + gid;

    for (int w = 0; w < nW; w++) {
        __syncthreads();
        stage_tile_tf32(Ws, Wp[w], 128);
        __syncthreads();

        float acc[2][8][4];
#pragma unroll
        for (int mt = 0; mt < 2; mt++)
#pragma unroll
            for (int nt = 0; nt < 8; nt++)
#pragma unroll
                for (int j = 0; j < 4; j++) acc[mt][nt][j] = 0.0f;

#pragma unroll
        for (int ks = 0; ks < 16; ks++) {
            const int k0 = ks * 8;
            uint32_t a[2][4], b[8][2];
#pragma unroll
            for (int mt = 0; mt < 2; mt++) {
                int r0 = rA + mt * 16;
                a[mt][0] = As[r0 * SMEM_LDA + k0 + tig];
                a[mt][1] = As[(r0 + 8) * SMEM_LDA + k0 + tig];
                a[mt][2] = As[r0 * SMEM_LDA + k0 + tig + 4];
                a[mt][3] = As[(r0 + 8) * SMEM_LDA + k0 + tig + 4];
            }
#pragma unroll
            for (int nt = 0; nt < 8; nt++) {
                int n = nB + nt * 8;
                b[nt][0] = Ws[n * SMEM_LDA + k0 + tig];
                b[nt][1] = Ws[n * SMEM_LDA + k0 + tig + 4];
            }
#pragma unroll
            for (int mt = 0; mt < 2; mt++)
#pragma unroll
                for (int nt = 0; nt < 8; nt++) {
                    asm volatile(
                        "mma.sync.aligned.m16n8k8.row.col.f32.tf32.tf32.f32 "
                        "{%0,%1,%2,%3}, {%4,%5,%6,%7}, {%8,%9}, {%0,%1,%2,%3};"
                        : "+f"(acc[mt][nt][0]), "+f"(acc[mt][nt][1]),
                          "+f"(acc[mt][nt][2]), "+f"(acc[mt][nt][3])
                        : "r"(a[mt][0]), "r"(a[mt][1]), "r"(a[mt][2]), "r"(a[mt][3]),
                          "r"(b[nt][0]), "r"(b[nt][1]));
                }
        }

        if (fuse && w == nW - 1) {
            // acc == Uch tile. Uih = C0, Uoh = C1 (written by THIS thread at the
            // SAME addresses in earlier iterations -> program-order visible, L2-hot).
            const float* Uih = Cp[0];
            const float* Uoh = Cp[1];
#pragma unroll
            for (int mt = 0; mt < 2; mt++) {
#pragma unroll
                for (int half = 0; half < 2; half++) {
                    int r = m0 + rA + mt * 16 + half * 8;
                    if (r >= M) continue;
                    size_t rowoff = (size_t)r * H;
#pragma unroll
                    for (int nt = 0; nt < 8; nt++) {
                        int col = wn * 64 + nt * 8 + tig * 2;
                        float uch0 = acc[mt][nt][half * 2 + 0];
                        float uch1 = acc[mt][nt][half * 2 + 1];
                        float2 wix = *(const float2*)(Wix + rowoff + col);
                        float2 uih = *(const float2*)(Uih + rowoff + col);
                        float2 wox = *(const float2*)(Wox + rowoff + col);
                        float2 uoh = *(const float2*)(Uoh + rowoff + col);
                        float2 wcx = *(const float2*)(Wcx + rowoff + col);
                        float2 fpcv = *(const float2*)(fpc + rowoff + col);
                        float i0 = sigmoidf(wix.x + uih.x), i1 = sigmoidf(wix.y + uih.y);
                        float ct0 = tanhf(wcx.x + uch0),    ct1 = tanhf(wcx.y + uch1);
                        float c0 = fmaf(i0, ct0, fpcv.x),   c1 = fmaf(i1, ct1, fpcv.y);
                        float o0 = sigmoidf(wox.x + uoh.x), o1 = sigmoidf(wox.y + uoh.y);
                        *(float2*)(out + rowoff + col) = make_float2(o0 * tanhf(c0), o1 * tanhf(c1));
                        *(float2*)(out + MH + rowoff + col) = make_float2(c0, c1);
                    }
                }
            }
        } else {
            const float* bias = bp[w];
            float* C = Cp[w];
#pragma unroll
            for (int mt = 0; mt < 2; mt++) {
                int r0 = m0 + rA + mt * 16;
#pragma unroll
                for (int nt = 0; nt < 8; nt++) {
                    int col = wn * 64 + nt * 8 + tig * 2;
                    float bx = 0.f, by = 0.f;
                    if (bias) { bx = __ldg(&bias[col]); by = __ldg(&bias[col + 1]); }
                    if (r0 < M) {
                        float2 v = make_float2(acc[mt][nt][0] + bx, acc[mt][nt][1] + by);
                        *(float2*)(C + (size_t)r0 * H + col) = v;
                    }
                    if (r0 + 8 < M) {
                        float2 v = make_float2(acc[mt][nt][2] + bx, acc[mt][nt][3] + by);
                        *(float2*)(C + (size_t)(r0 + 8) * H + col) = v;
                    }
                }
            }
        }
    }
}

// ---------------------------------------------------------------------------
// init: zero hhat/fpc (float4), segsum=0, segmax=-inf
// ---------------------------------------------------------------------------
__global__ void init_kernel(float4* __restrict__ hhat, float4* __restrict__ fpc,
                            float* __restrict__ segmax, float* __restrict__ segsum, int M) {
    int i = blockIdx.x * blockDim.x + threadIdx.x;
    int MH4 = M * (H / 4);
    float4 z = make_float4(0.f, 0.f, 0.f, 0.f);
    if (i < MH4) { hhat[i] = z; fpc[i] = z; }
    if (i < M)  { segmax[i] = __int_as_float(0xff800000); segsum[i] = 0.0f; }
}

// ---------------------------------------------------------------------------
// e[l] = tanh(Ah[chi] + Bx[ci]) . v ; segmax via atomic float-max. Warp/edge.
// ---------------------------------------------------------------------------
__global__ __launch_bounds__(256) void edge_e_kernel(
    const int* __restrict__ ci, const int* __restrict__ chi,
    const float* __restrict__ Ah, const float* __restrict__ Bx,
    const float* __restrict__ v, float* __restrict__ e,
    float* __restrict__ segmax, int L) {
    int w = (blockIdx.x * blockDim.x + threadIdx.x) >> 5;
    int lane = threadIdx.x & 31;
    if (w >= L) return;
    int c = __ldg(&ci[w]), ch = __ldg(&chi[w]);
    float4 a  = ((const float4*)(Ah + (size_t)ch * H))[lane];
    float4 b  = ((const float4*)(Bx + (size_t)c  * H))[lane];
    float4 vv = ((const float4*)v)[lane];
    float s = tanh_approx(a.x + b.x) * vv.x + tanh_approx(a.y + b.y) * vv.y
            + tanh_approx(a.z + b.z) * vv.z + tanh_approx(a.w + b.w) * vv.w;
#pragma unroll
    for (int o = 16; o > 0; o >>= 1) s += __shfl_xor_sync(0xffffffffu, s, o);
    if (lane == 0) {
        e[w] = s;
        atomicMaxFloat(&segmax[c], s);
    }
}

// ---------------------------------------------------------------------------
// xexp = exp(e - segmax[ci]); segsum += xexp. Thread/edge.
// ---------------------------------------------------------------------------
__global__ void edge_exp_kernel(const int* __restrict__ ci, const float* __restrict__ e,
                                const float* __restrict__ segmax, float* __restrict__ xexp,
                                float* __restrict__ segsum, int L) {
    int i = blockIdx.x * blockDim.x + threadIdx.x;
    if (i >= L) return;
    int c = ci[i];
    float xe = __expf(e[i] - segmax[c]);
    xexp[i] = xe;
    atomicAdd(&segsum[c], xe);
}

// ---------------------------------------------------------------------------
// hhat[ci] += attn * child_h[chi];  fpc[ci] += sigmoid(Wfx[ci]+Ufh[chi]) * child_c[chi]
// ---------------------------------------------------------------------------
__global__ __launch_bounds__(256) void edge_scatter_kernel(
    const int* __restrict__ ci, const int* __restrict__ chi,
    const float* __restrict__ xexp, const float* __restrict__ segsum,
    const float* __restrict__ child_h, const float* __restrict__ child_c,
    const float* __restrict__ Wfx, const float* __restrict__ Ufh,
    float* __restrict__ hhat, float* __restrict__ fpc, int L) {
    int w = (blockIdx.x * blockDim.x + threadIdx.x) >> 5;
    int lane = threadIdx.x & 31;
    if (w >= L) return;
    int c = __ldg(&ci[w]), ch = __ldg(&chi[w]);
    float attn = xexp[w] / (segsum[c] + EPS);
    float4 hv = ((const float4*)(child_h + (size_t)ch * H))[lane];
    float4 cv = ((const float4*)(child_c + (size_t)ch * H))[lane];
    float4 wf = ((const float4*)(Wfx + (size_t)c  * H))[lane];
    float4 uf = ((const float4*)(Ufh + (size_t)ch * H))[lane];
    float* hh = hhat + (size_t)c * H + lane * 4;
    float* fp = fpc  + (size_t)c * H + lane * 4;
    atomicAdd(hh + 0, attn * hv.x);
    atomicAdd(hh + 1, attn * hv.y);
    atomicAdd(hh + 2, attn * hv.z);
    atomicAdd(hh + 3, attn * hv.w);
    atomicAdd(fp + 0, sigmoidf(wf.x + uf.x) * cv.x);
    atomicAdd(fp + 1, sigmoidf(wf.y + uf.y) * cv.y);
    atomicAdd(fp + 2, sigmoidf(wf.z + uf.z) * cv.z);
    atomicAdd(fp + 3, sigmoidf(wf.w + uf.w) * cv.w);
}

// ---------------------------------------------------------------------------
extern "C" void kernel_launch(void* const* d_in, const int* in_sizes, int n_in,
                              void* d_out, int out_size) {
    const float* x_emb   = (const float*)d_in[0];
    const float* child_h = (const float*)d_in[1];
    const float* child_c = (const float*)d_in[2];
    const int*   ci      = (const int*)d_in[3];
    const int*   chi     = (const int*)d_in[4];
    const float* Wi_w = (const float*)d_in[5];
    const float* Ui_w = (const float*)d_in[6];
    const float* Wf_w = (const float*)d_in[7];
    const float* Uf_w = (const float*)d_in[8];
    const float* Wo_w = (const float*)d_in[9];
    const float* Uo_w = (const float*)d_in[10];
    const float* Wc_w = (const float*)d_in[11];
    const float* Uc_w = (const float*)d_in[12];
    const float* Wa_w = (const float*)d_in[13];
    const float* Ua_w = (const float*)d_in[14];
    const float* Wi_b = (const float*)d_in[15];
    const float* Wf_b = (const float*)d_in[16];
    const float* Wo_b = (const float*)d_in[17];
    const float* Wc_b = (const float*)d_in[18];
    const float* Wa_b = (const float*)d_in[19];
    const float* v_w  = (const float*)d_in[20];

    const int M  = in_sizes[0] / H;
    const int L  = in_sizes[3];
    const int MH = M * H;

    float* s = nullptr;
    cudaGetSymbolAddress((void**)&s, g_scratch);
    float* Ah   = s + 0  * (size_t)MH_MAX;
    float* Bx   = s + 1  * (size_t)MH_MAX;
    float* Wfx  = s + 2  * (size_t)MH_MAX;
    float* Ufh  = s + 3  * (size_t)MH_MAX;
    float* Wix  = s + 4  * (size_t)MH_MAX;
    float* Wox  = s + 5  * (size_t)MH_MAX;
    float* Wcx  = s + 6  * (size_t)MH_MAX;
    float* hhat = s + 7  * (size_t)MH_MAX;
    float* fpc  = s + 8  * (size_t)MH_MAX;
    float* Uih  = s + 9  * (size_t)MH_MAX;
    float* Uoh  = s + 10 * (size_t)MH_MAX;
    float* e_v    = s + 12 * (size_t)MH_MAX;
    float* xexp   = e_v + L_MAX;
    float* segmax = xexp + L_MAX;
    float* segsum = segmax + M_MAX;

    cudaFuncSetAttribute(gemm_mma_kernel, cudaFuncAttributeMaxDynamicSharedMemorySize, GEMM_DSMEM);

    const int gg = (M + 127) / 128;
    const int eb = (L + 7) / 8;

    init_kernel<<<(MH / 4 + 255) / 256, 256>>>((float4*)hhat, (float4*)fpc, segmax, segsum, M);

    // x_emb GEMMs: Wi, Wf, Wo, Wc, Ua (A tile staged once, 5 weights)
    gemm_mma_kernel<<<gg, 256, GEMM_DSMEM>>>(
        x_emb, M, 5,
        Wi_w, Wf_w, Wo_w, Wc_w, Ua_w,
        Wi_b, Wf_b, Wo_b, Wc_b, nullptr,
        Wix, Wfx, Wox, Wcx, Bx,
        nullptr, nullptr, nullptr, nullptr, nullptr, 0);

    // child_h GEMMs: Wa (+bias), Uf
    gemm_mma_kernel<<<gg, 256, GEMM_DSMEM>>>(
        child_h, M, 2,
        Wa_w, Uf_w, nullptr, nullptr, nullptr,
        Wa_b, nullptr, nullptr, nullptr, nullptr,
        Ah, Ufh, nullptr, nullptr, nullptr,
        nullptr, nullptr, nullptr, nullptr, nullptr, 0);

    // segment attention
    edge_e_kernel<<<eb, 256>>>(ci, chi, Ah, Bx, v_w, e_v, segmax, L);
    edge_exp_kernel<<<(L + 255) / 256, 256>>>(ci, e_v, segmax, xexp, segsum, L);
    edge_scatter_kernel<<<eb, 256>>>(ci, chi, xexp, segsum, child_h, child_c,
                                     Wfx, Ufh, hhat, fpc, L);

    // hhat GEMMs: Ui, Uo, Uc — fused LSTM-gate epilogue on the Uc pass
    gemm_mma_kernel<<<gg, 256, GEMM_DSMEM>>>(
        hhat, M, 3,
        Ui_w, Uo_w, Uc_w, nullptr, nullptr,
        nullptr, nullptr, nullptr, nullptr, nullptr,
        Uih, Uoh, nullptr, nullptr, nullptr,
        Wix, Wox, Wcx, fpc, (float*)d_out, 1);
}

// round 10
// speedup vs baseline: 1.3781x; 1.3781x over previous
#include <cuda_runtime.h>
#include <math.h>
#include <stdint.h>

#define H 128
#define EPS 1e-9f
#define M_MAX 50000
#define L_MAX 400000
#define MH_MAX (M_MAX * H)

// float scratch: 12 slots of MH_MAX + e[L]
__device__ float g_scratch[12 * (size_t)MH_MAX + (size_t)L_MAX];
// int scratch for CSR: order[L], counts[M], offsets[M+1], cursor[M]
__device__ int g_csr[(size_t)L_MAX + 3 * (size_t)M_MAX + 8];

__device__ __forceinline__ float sigmoid_fast(float x) {
    return __fdividef(1.0f, 1.0f + __expf(-x));
}

__device__ __forceinline__ float tanh_approx(float x) {
    float y;
    asm("tanh.approx.f32 %0, %1;" : "=f"(y) : "f"(x));
    return y;
}

__device__ __forceinline__ uint32_t tf32_rna(float x) {
    uint32_t o;
    asm("cvt.rna.tf32.f32 %0, %1;" : "=r"(o) : "f"(x));
    return o;
}

// ===========================================================================
// Tensor-core GEMM via mma.sync tf32 (HMMA path, compute_103-safe PTX).
// C_w[M,128] = A[M,128] @ W_w[128,128]^T (+ b_w), up to 5 weights per launch
// sharing the staged A tile.
// ===========================================================================
#define SMEM_LDA 132
#define GEMM_DSMEM (2 * 128 * SMEM_LDA * 4)

__device__ __forceinline__ void stage_tile_tf32(
    uint32_t* dst, const float* __restrict__ src, int rows_valid) {
    int tid = threadIdx.x;
#pragma unroll
    for (int i = tid; i < 128 * 32; i += 256) {
        int r = i >> 5, c4 = i & 31;
        float4 v = make_float4(0.f, 0.f, 0.f, 0.f);
        if (r < rows_valid) v = ((const float4*)(src + (size_t)r * H))[c4];
        uint4 u;
        u.x = tf32_rna(v.x); u.y = tf32_rna(v.y);
        u.z = tf32_rna(v.z); u.w = tf32_rna(v.w);
        *(uint4*)(dst + r * SMEM_LDA + c4 * 4) = u;
    }
}

__global__ __launch_bounds__(256, 1) void gemm_mma_kernel(
    const float* __restrict__ A, int M, int nW,
    const float* W0, const float* W1, const float* W2, const float* W3, const float* W4,
    const float* b0, const float* b1, const float* b2, const float* b3, const float* b4,
    float* C0, float* C1, float* C2, float* C3, float* C4) {
    extern __shared__ uint32_t sm[];
    uint32_t* As = sm;
    uint32_t* Ws = sm + 128 * SMEM_LDA;

    const float* Wp[5] = {W0, W1, W2, W3, W4};
    const float* bp[5] = {b0, b1, b2, b3, b4};
    float*       Cp[5] = {C0, C1, C2, C3, C4};

    const int tid = threadIdx.x;
    const int wid = tid >> 5, lane = tid & 31;
    const int wm = wid & 3, wn = wid >> 2;
    const int gid = lane >> 2, tig = lane & 3;
    const int m0 = blockIdx.x * 128;
    const int rows = min(128, M - m0);

    stage_tile_tf32(As, A + (size_t)m0 * H, rows);

    const int rA = wm * 32 + gid;
    const int nB = wn * 64 + gid;

    for (int w = 0; w < nW; w++) {
        __syncthreads();
        stage_tile_tf32(Ws, Wp[w], 128);
        __syncthreads();

        float acc[2][8][4];
#pragma unroll
        for (int mt = 0; mt < 2; mt++)
#pragma unroll
            for (int nt = 0; nt < 8; nt++)
#pragma unroll
                for (int j = 0; j < 4; j++) acc[mt][nt][j] = 0.0f;

#pragma unroll
        for (int ks = 0; ks < 16; ks++) {
            const int k0 = ks * 8;
            uint32_t a[2][4], b[8][2];
#pragma unroll
            for (int mt = 0; mt < 2; mt++) {
                int r0 = rA + mt * 16;
                a[mt][0] = As[r0 * SMEM_LDA + k0 + tig];
                a[mt][1] = As[(r0 + 8) * SMEM_LDA + k0 + tig];
                a[mt][2] = As[r0 * SMEM_LDA + k0 + tig + 4];
                a[mt][3] = As[(r0 + 8) * SMEM_LDA + k0 + tig + 4];
            }
#pragma unroll
            for (int nt = 0; nt < 8; nt++) {
                int n = nB + nt * 8;
                b[nt][0] = Ws[n * SMEM_LDA + k0 + tig];
                b[nt][1] = Ws[n * SMEM_LDA + k0 + tig + 4];
            }
#pragma unroll
            for (int mt = 0; mt < 2; mt++)
#pragma unroll
                for (int nt = 0; nt < 8; nt++) {
                    asm volatile(
                        "mma.sync.aligned.m16n8k8.row.col.f32.tf32.tf32.f32 "
                        "{%0,%1,%2,%3}, {%4,%5,%6,%7}, {%8,%9}, {%0,%1,%2,%3};"
                        : "+f"(acc[mt][nt][0]), "+f"(acc[mt][nt][1]),
                          "+f"(acc[mt][nt][2]), "+f"(acc[mt][nt][3])
                        : "r"(a[mt][0]), "r"(a[mt][1]), "r"(a[mt][2]), "r"(a[mt][3]),
                          "r"(b[nt][0]), "r"(b[nt][1]));
                }
        }

        const float* bias = bp[w];
        float* C = Cp[w];
#pragma unroll
        for (int mt = 0; mt < 2; mt++) {
            int r0 = m0 + rA + mt * 16;
#pragma unroll
            for (int nt = 0; nt < 8; nt++) {
                int col = wn * 64 + nt * 8 + tig * 2;
                float bx = 0.f, by = 0.f;
                if (bias) { bx = __ldg(&bias[col]); by = __ldg(&bias[col + 1]); }
                if (r0 < M) {
                    float2 v = make_float2(acc[mt][nt][0] + bx, acc[mt][nt][1] + by);
                    *(float2*)(C + (size_t)r0 * H + col) = v;
                }
                if (r0 + 8 < M) {
                    float2 v = make_float2(acc[mt][nt][2] + bx, acc[mt][nt][3] + by);
                    *(float2*)(C + (size_t)(r0 + 8) * H + col) = v;
                }
            }
        }
    }
}

// ===========================================================================
// CSR build: counts/cursor zero -> histogram -> 1-block scan -> rank scatter
// ===========================================================================
__global__ void csr_zero_kernel(int* __restrict__ counts, int* __restrict__ cursor, int M) {
    int i = blockIdx.x * blockDim.x + threadIdx.x;
    if (i < M) { counts[i] = 0; cursor[i] = 0; }
}

__global__ void hist_kernel(const int* __restrict__ ci, int* __restrict__ counts, int L) {
    int i = blockIdx.x * blockDim.x + threadIdx.x;
    if (i < L) atomicAdd(&counts[ci[i]], 1);
}

__global__ __launch_bounds__(1024) void scan_kernel(
    const int* __restrict__ counts, int* __restrict__ offsets, int M) {
    __shared__ int ss[1024];
    int t = threadIdx.x;
    int chunk = (M + 1023) >> 10;
    int lo = t * chunk, hi = min(lo + chunk, M);
    int s = 0;
    for (int i = lo; i < hi; i++) s += counts[i];
    ss[t] = s;
    __syncthreads();
#pragma unroll
    for (int off = 1; off < 1024; off <<= 1) {
        int v = (t >= off) ? ss[t - off] : 0;
        __syncthreads();
        ss[t] += v;
        __syncthreads();
    }
    int pre = (t > 0) ? ss[t - 1] : 0;
    for (int i = lo; i < hi; i++) { offsets[i] = pre; pre += counts[i]; }
    if (t == 0) offsets[M] = ss[1023];
}

__global__ void rank_kernel(const int* __restrict__ ci, const int* __restrict__ offsets,
                            int* __restrict__ cursor, int* __restrict__ order, int L) {
    int i = blockIdx.x * blockDim.x + threadIdx.x;
    if (i >= L) return;
    int c = ci[i];
    int pos = offsets[c] + atomicAdd(&cursor[c], 1);
    order[pos] = i;
}

// ---------------------------------------------------------------------------
// e[l] = tanh(Ah[chi] + Bx[ci]) . v  (no atomics). Warp/edge.
// ---------------------------------------------------------------------------
__global__ __launch_bounds__(256) void edge_e_kernel(
    const int* __restrict__ ci, const int* __restrict__ chi,
    const float* __restrict__ Ah, const float* __restrict__ Bx,
    const float* __restrict__ v, float* __restrict__ e, int L) {
    int w = (blockIdx.x * blockDim.x + threadIdx.x) >> 5;
    int lane = threadIdx.x & 31;
    if (w >= L) return;
    int c = __ldg(&ci[w]), ch = __ldg(&chi[w]);
    float4 a  = ((const float4*)(Ah + (size_t)ch * H))[lane];
    float4 b  = ((const float4*)(Bx + (size_t)c  * H))[lane];
    float4 vv = ((const float4*)v)[lane];
    float s = tanh_approx(a.x + b.x) * vv.x + tanh_approx(a.y + b.y) * vv.y
            + tanh_approx(a.z + b.z) * vv.z + tanh_approx(a.w + b.w) * vv.w;
#pragma unroll
    for (int o = 16; o > 0; o >>= 1) s += __shfl_xor_sync(0xffffffffu, s, o);
    if (lane == 0) e[w] = s;
}

// ---------------------------------------------------------------------------
// Warp-per-node segment softmax + weighted gathers (no atomics):
//   hhat[m] = (sum_j exp(e_j - max) * child_h[chi_j]) / (sum_j exp(..) + EPS)
//   fpc[m]  =  sum_j sigmoid(Wfx[m] + Ufh[chi_j]) * child_c[chi_j]
// ---------------------------------------------------------------------------
__global__ __launch_bounds__(256) void node_kernel(
    const int* __restrict__ off, const int* __restrict__ order,
    const float* __restrict__ e, const int* __restrict__ chi,
    const float* __restrict__ child_h, const float* __restrict__ child_c,
    const float* __restrict__ Wfx, const float* __restrict__ Ufh,
    float* __restrict__ hhat, float* __restrict__ fpc, int M) {
    int m = (blockIdx.x * blockDim.x + threadIdx.x) >> 5;
    int lane = threadIdx.x & 31;
    if (m >= M) return;
    int s = off[m], tend = off[m + 1];

    float4 wfx = ((const float4*)(Wfx + (size_t)m * H))[lane];
    float4 ha = make_float4(0.f, 0.f, 0.f, 0.f);
    float4 fa = make_float4(0.f, 0.f, 0.f, 0.f);

    // pass 1: segment max of e
    float mx = __int_as_float(0xff800000);
    for (int base = s; base < tend; base += 32) {
        int j = base + lane;
        float ev = (j < tend) ? e[order[j]] : __int_as_float(0xff800000);
        mx = fmaxf(mx, ev);
    }
#pragma unroll
    for (int o = 16; o > 0; o >>= 1) mx = fmaxf(mx, __shfl_xor_sync(0xffffffffu, mx, o));

    // pass 2: accumulate (division by sum deferred to the end)
    float sum = 0.0f;
    for (int base = s; base < tend; base += 32) {
        int j = base + lane;
        int eid = (j < tend) ? order[j] : 0;
        int child = (j < tend) ? chi[eid] : 0;
        float ex = (j < tend) ? __expf(e[eid] - mx) : 0.0f;
        sum += ex;
        int nin = min(32, tend - base);
        for (int q = 0; q < nin; q++) {
            float exq = __shfl_sync(0xffffffffu, ex, q);
            int   chq = __shfl_sync(0xffffffffu, child, q);
            float4 hv = ((const float4*)(child_h + (size_t)chq * H))[lane];
            float4 cv = ((const float4*)(child_c + (size_t)chq * H))[lane];
            float4 uf = ((const float4*)(Ufh + (size_t)chq * H))[lane];
            ha.x += exq * hv.x; ha.y += exq * hv.y;
            ha.z += exq * hv.z; ha.w += exq * hv.w;
            fa.x += sigmoid_fast(wfx.x + uf.x) * cv.x;
            fa.y += sigmoid_fast(wfx.y + uf.y) * cv.y;
            fa.z += sigmoid_fast(wfx.z + uf.z) * cv.z;
            fa.w += sigmoid_fast(wfx.w + uf.w) * cv.w;
        }
    }
#pragma unroll
    for (int o = 16; o > 0; o >>= 1) sum += __shfl_xor_sync(0xffffffffu, sum, o);

    float inv = __fdividef(1.0f, sum + EPS);
    ((float4*)(hhat + (size_t)m * H))[lane] =
        make_float4(ha.x * inv, ha.y * inv, ha.z * inv, ha.w * inv);
    ((float4*)(fpc + (size_t)m * H))[lane] = fa;
}

// ---------------------------------------------------------------------------
// Final gates + outputs: out[0:MH]=h, out[MH:2MH]=c
// ---------------------------------------------------------------------------
__global__ void final_kernel(
    const float* __restrict__ Wix, const float* __restrict__ Uih,
    const float* __restrict__ Wox, const float* __restrict__ Uoh,
    const float* __restrict__ Wcx, const float* __restrict__ Uch,
    const float* __restrict__ fpc, float* __restrict__ out, int MH) {
    int i = blockIdx.x * blockDim.x + threadIdx.x;
    if (i >= MH) return;
    float iv = sigmoid_fast(Wix[i] + Uih[i]);
    float ct = tanhf(Wcx[i] + Uch[i]);
    float cc = fmaf(iv, ct, fpc[i]);
    float ov = sigmoid_fast(Wox[i] + Uoh[i]);
    out[i] = ov * tanhf(cc);
    out[MH + i] = cc;
}

// ---------------------------------------------------------------------------
extern "C" void kernel_launch(void* const* d_in, const int* in_sizes, int n_in,
                              void* d_out, int out_size) {
    const float* x_emb   = (const float*)d_in[0];
    const float* child_h = (const float*)d_in[1];
    const float* child_c = (const float*)d_in[2];
    const int*   ci      = (const int*)d_in[3];
    const int*   chi     = (const int*)d_in[4];
    const float* Wi_w = (const float*)d_in[5];
    const float* Ui_w = (const float*)d_in[6];
    const float* Wf_w = (const float*)d_in[7];
    const float* Uf_w = (const float*)d_in[8];
    const float* Wo_w = (const float*)d_in[9];
    const float* Uo_w = (const float*)d_in[10];
    const float* Wc_w = (const float*)d_in[11];
    const float* Uc_w = (const float*)d_in[12];
    const float* Wa_w = (const float*)d_in[13];
    const float* Ua_w = (const float*)d_in[14];
    const float* Wi_b = (const float*)d_in[15];
    const float* Wf_b = (const float*)d_in[16];
    const float* Wo_b = (const float*)d_in[17];
    const float* Wc_b = (const float*)d_in[18];
    const float* Wa_b = (const float*)d_in[19];
    const float* v_w  = (const float*)d_in[20];

    const int M  = in_sizes[0] / H;
    const int L  = in_sizes[3];
    const int MH = M * H;

    float* s = nullptr;
    cudaGetSymbolAddress((void**)&s, g_scratch);
    int* csr = nullptr;
    cudaGetSymbolAddress((void**)&csr, g_csr);

    float* Ah   = s + 0  * (size_t)MH_MAX;
    float* Bx   = s + 1  * (size_t)MH_MAX;
    float* Wfx  = s + 2  * (size_t)MH_MAX;
    float* Ufh  = s + 3  * (size_t)MH_MAX;
    float* Wix  = s + 4  * (size_t)MH_MAX;
    float* Wox  = s + 5  * (size_t)MH_MAX;
    float* Wcx  = s + 6  * (size_t)MH_MAX;
    float* hhat = s + 7  * (size_t)MH_MAX;
    float* fpc  = s + 8  * (size_t)MH_MAX;
    float* Uih  = s + 9  * (size_t)MH_MAX;
    float* Uoh  = s + 10 * (size_t)MH_MAX;
    float* Uch  = s + 11 * (size_t)MH_MAX;
    float* e_v  = s + 12 * (size_t)MH_MAX;

    int* order   = csr;
    int* counts  = csr + (size_t)L_MAX;
    int* offsets = counts + (size_t)M_MAX;
    int* cursor  = offsets + (size_t)M_MAX + 2;

    cudaFuncSetAttribute(gemm_mma_kernel, cudaFuncAttributeMaxDynamicSharedMemorySize, GEMM_DSMEM);

    const int gg = (M + 127) / 128;
    const int eb = (L + 7) / 8;

    // CSR build (independent of GEMMs)
    csr_zero_kernel<<<(M + 255) / 256, 256>>>(counts, cursor, M);
    hist_kernel<<<(L + 255) / 256, 256>>>(ci, counts, L);
    scan_kernel<<<1, 1024>>>(counts, offsets, M);
    rank_kernel<<<(L + 255) / 256, 256>>>(ci, offsets, cursor, order, L);

    // x_emb GEMMs: Wi, Wf, Wo, Wc, Ua
    gemm_mma_kernel<<<gg, 256, GEMM_DSMEM>>>(
        x_emb, M, 5,
        Wi_w, Wf_w, Wo_w, Wc_w, Ua_w,
        Wi_b, Wf_b, Wo_b, Wc_b, nullptr,
        Wix, Wfx, Wox, Wcx, Bx);

    // child_h GEMMs: Wa (+bias), Uf
    gemm_mma_kernel<<<gg, 256, GEMM_DSMEM>>>(
        child_h, M, 2,
        Wa_w, Uf_w, nullptr, nullptr, nullptr,
        Wa_b, nullptr, nullptr, nullptr, nullptr,
        Ah, Ufh, nullptr, nullptr, nullptr);

    // attention scores, then node-centric segment softmax + gathers
    edge_e_kernel<<<eb, 256>>>(ci, chi, Ah, Bx, v_w, e_v, L);
    node_kernel<<<(M * 32 + 255) / 256, 256>>>(
        offsets, order, e_v, chi, child_h, child_c, Wfx, Ufh, hhat, fpc, M);

    // hhat GEMMs: Ui, Uo, Uc
    gemm_mma_kernel<<<gg, 256, GEMM_DSMEM>>>(
        hhat, M, 3,
        Ui_w, Uo_w, Uc_w, nullptr, nullptr,
        nullptr, nullptr, nullptr, nullptr, nullptr,
        Uih, Uoh, Uch, nullptr, nullptr);

    final_kernel<<<(MH + 255) / 256, 256>>>(Wix, Uih, Wox, Uoh, Wcx, Uch, fpc,
                                            (float*)d_out, MH);
}